// round 1
// baseline (speedup 1.0000x reference)
#include <cuda_runtime.h>
#include <math.h>

// Problem constants (B=1)
#define SEQ   2048
#define HID   4096
#define NHEAD 32
#define HDIM  128
#define QKV_N 12288            // 3*HID
#define INV_NORM 0.08838834764831845f   // 1/sqrt(128)

// Scratch buffers (static device globals; runtime alloc is forbidden)
static __device__ float g_qkv[(size_t)SEQ * QKV_N];   // [S, NH*3*HD] BLOOM interleaved
static __device__ float g_ctx[(size_t)SEQ * HID];     // [S, NH*HD]

// ---------------------------------------------------------------------------
// TN GEMM: C[m,n] = sum_k A[m,k] * B[n,k] + bias[n] (+ add[m,n] if add!=nullptr)
// Both A and B are K-contiguous (row-major [M,K] and [N,K]).
// 128x128 block, BK=16, 256 threads, 8x8 micro-tile per thread.
// ---------------------------------------------------------------------------
__global__ __launch_bounds__(256, 2)
void gemm_tn(const float* __restrict__ A, const float* __restrict__ B,
             const float* __restrict__ bias, const float* __restrict__ add,
             float* __restrict__ C, int M, int N, int K)
{
    __shared__ float As[16][128];   // As[k][m]
    __shared__ float Bs[16][128];   // Bs[k][n]

    const int tid = threadIdx.x;
    const int bm = blockIdx.y * 128;
    const int bn = blockIdx.x * 128;

    // compute-thread mapping: 8 warps in 4(m) x 2(n); lane in 4(m) x 8(n); 8x8 per thread
    const int w    = tid >> 5;
    const int lane = tid & 31;
    const int wr   = w & 3;          // 0..3  -> 32 rows each
    const int wc   = w >> 2;         // 0..1  -> 64 cols each
    const int la_m = lane >> 3;      // 0..3
    const int la_n = lane & 7;       // 0..7
    const int am   = wr * 32 + la_m * 8;   // m offset within block tile
    const int an   = wc * 64 + la_n * 8;   // n offset within block tile

    // loader mapping: each thread loads 2 float4 of A and 2 float4 of B per tile
    const int lr = tid >> 2;         // 0..63
    const int lc = (tid & 3) * 4;    // 0,4,8,12

    const float* Ap0 = A + (size_t)(bm + lr)      * K + lc;
    const float* Ap1 = A + (size_t)(bm + lr + 64) * K + lc;
    const float* Bp0 = B + (size_t)(bn + lr)      * K + lc;
    const float* Bp1 = B + (size_t)(bn + lr + 64) * K + lc;

    float acc[8][8];
#pragma unroll
    for (int i = 0; i < 8; i++)
#pragma unroll
        for (int j = 0; j < 8; j++) acc[i][j] = 0.0f;

    for (int k0 = 0; k0 < K; k0 += 16) {
        // prefetch from global before barrier (overlaps previous tile compute)
        const float4 a0 = *(const float4*)(Ap0 + k0);
        const float4 a1 = *(const float4*)(Ap1 + k0);
        const float4 b0 = *(const float4*)(Bp0 + k0);
        const float4 b1 = *(const float4*)(Bp1 + k0);

        __syncthreads();   // previous compute done before smem overwrite
        As[lc + 0][lr] = a0.x; As[lc + 1][lr] = a0.y;
        As[lc + 2][lr] = a0.z; As[lc + 3][lr] = a0.w;
        As[lc + 0][lr + 64] = a1.x; As[lc + 1][lr + 64] = a1.y;
        As[lc + 2][lr + 64] = a1.z; As[lc + 3][lr + 64] = a1.w;
        Bs[lc + 0][lr] = b0.x; Bs[lc + 1][lr] = b0.y;
        Bs[lc + 2][lr] = b0.z; Bs[lc + 3][lr] = b0.w;
        Bs[lc + 0][lr + 64] = b1.x; Bs[lc + 1][lr + 64] = b1.y;
        Bs[lc + 2][lr + 64] = b1.z; Bs[lc + 3][lr + 64] = b1.w;
        __syncthreads();

#pragma unroll
        for (int kk = 0; kk < 16; kk++) {
            const float4 av0 = *(const float4*)&As[kk][am];
            const float4 av1 = *(const float4*)&As[kk][am + 4];
            const float4 bv0 = *(const float4*)&Bs[kk][an];
            const float4 bv1 = *(const float4*)&Bs[kk][an + 4];
            const float a[8] = {av0.x, av0.y, av0.z, av0.w, av1.x, av1.y, av1.z, av1.w};
            const float b[8] = {bv0.x, bv0.y, bv0.z, bv0.w, bv1.x, bv1.y, bv1.z, bv1.w};
#pragma unroll
            for (int i = 0; i < 8; i++)
#pragma unroll
                for (int j = 0; j < 8; j++)
                    acc[i][j] += a[i] * b[j];
        }
    }

    // epilogue
    const int ncol = bn + an;
    const float4 bb0 = *(const float4*)&bias[ncol];
    const float4 bb1 = *(const float4*)&bias[ncol + 4];
    const float bcol[8] = {bb0.x, bb0.y, bb0.z, bb0.w, bb1.x, bb1.y, bb1.z, bb1.w};

#pragma unroll
    for (int i = 0; i < 8; i++) {
        const int m = bm + am + i;
        float o[8];
#pragma unroll
        for (int j = 0; j < 8; j++) o[j] = acc[i][j] + bcol[j];
        if (add != nullptr) {
            const float4 r0 = *(const float4*)&add[(size_t)m * N + ncol];
            const float4 r1 = *(const float4*)&add[(size_t)m * N + ncol + 4];
            o[0] += r0.x; o[1] += r0.y; o[2] += r0.z; o[3] += r0.w;
            o[4] += r1.x; o[5] += r1.y; o[6] += r1.z; o[7] += r1.w;
        }
        float4 s0 = make_float4(o[0], o[1], o[2], o[3]);
        float4 s1 = make_float4(o[4], o[5], o[6], o[7]);
        *(float4*)&C[(size_t)m * N + ncol]     = s0;
        *(float4*)&C[(size_t)m * N + ncol + 4] = s1;
    }
}

// ---------------------------------------------------------------------------
// Flash-style causal attention with ALiBi.
// grid = (S/64 query blocks, NH heads), 256 threads.
// Thread layout: warp w (0..7) covers queries w*8..w*8+7 of the 64-query block;
// within warp, lane = qq*4 + g : qq = query-in-warp (0..7), g = dim group (0..3,
// each owning 32 of the 128 head dims).
// qkv layout per row s: [h*384 + {0:q,128:k,256:v} + d]
// ---------------------------------------------------------------------------
__global__ __launch_bounds__(256, 2)
void attn_kernel(const float* __restrict__ qkv, const float* __restrict__ alibi,
                 float* __restrict__ ctx)
{
    __shared__ float Ks[32][HDIM];
    __shared__ float Vs[32][HDIM];

    const int h   = blockIdx.y;
    const int qb  = blockIdx.x;           // query block (64 queries)
    const int tid = threadIdx.x;
    const int w    = tid >> 5;
    const int lane = tid & 31;
    const int qq = lane >> 2;
    const int g  = lane & 3;
    const int q  = qb * 64 + w * 8 + qq;  // global query index

    // load + prescale q
    const float* qrow = qkv + (size_t)q * QKV_N + h * 384 + g * 32;
    float qreg[32];
#pragma unroll
    for (int d = 0; d < 32; d += 4) {
        const float4 v4 = *(const float4*)(qrow + d);
        qreg[d + 0] = v4.x * INV_NORM;
        qreg[d + 1] = v4.y * INV_NORM;
        qreg[d + 2] = v4.z * INV_NORM;
        qreg[d + 3] = v4.w * INV_NORM;
    }

    float acc[32];
#pragma unroll
    for (int d = 0; d < 32; d++) acc[d] = 0.0f;
    float mrun = -INFINITY;
    float lrun = 0.0f;

    const float* alibi_h = alibi + (size_t)h * SEQ;
    const int kv_end = qb * 64 + 64;      // exclusive; causal upper bound for this block

    for (int kb = 0; kb < kv_end; kb += 32) {
        // cooperative K/V tile load (coalesced, 512B rows)
        for (int i = tid; i < 32 * HDIM; i += 256) {
            const int r = i >> 7, c = i & 127;
            const float* base = qkv + (size_t)(kb + r) * QKV_N + h * 384;
            Ks[r][c] = base[128 + c];
            Vs[r][c] = base[256 + c];
        }
        __syncthreads();

#pragma unroll 1
        for (int jc = 0; jc < 32; jc += 8) {
            float s[8];
#pragma unroll
            for (int jj = 0; jj < 8; jj++) s[jj] = 0.0f;

#pragma unroll
            for (int d = 0; d < 32; d += 4) {
#pragma unroll
                for (int jj = 0; jj < 8; jj++) {
                    const float4 k4 = *(const float4*)&Ks[jc + jj][g * 32 + d];
                    s[jj] += qreg[d] * k4.x + qreg[d + 1] * k4.y
                           + qreg[d + 2] * k4.z + qreg[d + 3] * k4.w;
                }
            }
            // reduce partial dots across the 4 dim-group threads (lanes qq*4..qq*4+3)
#pragma unroll
            for (int jj = 0; jj < 8; jj++) {
                s[jj] += __shfl_xor_sync(0xffffffffu, s[jj], 1);
                s[jj] += __shfl_xor_sync(0xffffffffu, s[jj], 2);
            }
            // alibi + causal mask, local max
            float mloc = -INFINITY;
#pragma unroll
            for (int jj = 0; jj < 8; jj++) {
                const int jg = kb + jc + jj;
                s[jj] = (jg <= q) ? (s[jj] + alibi_h[jg]) : -INFINITY;
                mloc = fmaxf(mloc, s[jj]);
            }
            // rescale only when the running max moves
            if (mloc > mrun) {
                const float scale = __expf(mrun - mloc);
                mrun = mloc;
                lrun *= scale;
#pragma unroll
                for (int d = 0; d < 32; d++) acc[d] *= scale;
            }
#pragma unroll
            for (int jj = 0; jj < 8; jj++) {
                const float p = __expf(s[jj] - mrun);   // expf(-inf)=0 for masked
                lrun += p;
#pragma unroll
                for (int d = 0; d < 32; d += 4) {
                    const float4 v4 = *(const float4*)&Vs[jc + jj][g * 32 + d];
                    acc[d + 0] += p * v4.x;
                    acc[d + 1] += p * v4.y;
                    acc[d + 2] += p * v4.z;
                    acc[d + 3] += p * v4.w;
                }
            }
        }
        __syncthreads();
    }

    const float inv_l = 1.0f / lrun;
    float* out = ctx + (size_t)q * HID + h * HDIM + g * 32;
#pragma unroll
    for (int d = 0; d < 32; d += 4) {
        float4 o = make_float4(acc[d] * inv_l, acc[d + 1] * inv_l,
                               acc[d + 2] * inv_l, acc[d + 3] * inv_l);
        *(float4*)(out + d) = o;
    }
}

// ---------------------------------------------------------------------------
// Launch
// inputs: 0 hidden_states [1,2048,4096] f32, 1 residual, 2 alibi [32,1,2048] f32,
//         3 attention_mask (unused), 4 W_qkv [12288,4096], 5 b_qkv [12288],
//         6 W_dense [4096,4096], 7 b_dense [4096]
// ---------------------------------------------------------------------------
extern "C" void kernel_launch(void* const* d_in, const int* in_sizes, int n_in,
                              void* d_out, int out_size)
{
    const float* hs       = (const float*)d_in[0];
    const float* residual = (const float*)d_in[1];
    const float* alibi    = (const float*)d_in[2];
    const float* Wqkv     = (const float*)d_in[4];
    const float* bqkv     = (const float*)d_in[5];
    const float* Wd       = (const float*)d_in[6];
    const float* bd       = (const float*)d_in[7];
    float* out = (float*)d_out;

    float* qkv_buf = nullptr;
    float* ctx_buf = nullptr;
    cudaGetSymbolAddress((void**)&qkv_buf, g_qkv);
    cudaGetSymbolAddress((void**)&ctx_buf, g_ctx);

    // 1) fused QKV projection: [2048,4096] @ [12288,4096]^T + b_qkv
    {
        dim3 grid(QKV_N / 128, SEQ / 128);
        gemm_tn<<<grid, 256>>>(hs, Wqkv, bqkv, nullptr, qkv_buf, SEQ, QKV_N, HID);
    }
    // 2) attention
    {
        dim3 grid(SEQ / 64, NHEAD);
        attn_kernel<<<grid, 256>>>(qkv_buf, alibi, ctx_buf);
    }
    // 3) dense projection + bias + residual
    {
        dim3 grid(HID / 128, SEQ / 128);
        gemm_tn<<<grid, 256>>>(ctx_buf, Wd, bd, residual, out, SEQ, HID, HID);
    }
}

// round 6
// speedup vs baseline: 1.3162x; 1.3162x over previous
#include <cuda_runtime.h>
#include <cuda_bf16.h>
#include <math.h>
#include <stdint.h>

// Problem constants (B=1)
#define SEQ   2048
#define HID   4096
#define NHEAD 32
#define HDIM  128
#define QKV_N 12288            // 3*HID
#define INV_NORM 0.08838834764831845f   // 1/sqrt(128)

// Scratch buffers (static device globals; runtime alloc is forbidden)
static __device__ float g_qkv[(size_t)SEQ * QKV_N];   // [S, NH*3*HD] BLOOM interleaved
static __device__ float g_ctx[(size_t)SEQ * HID];     // [S, NH*HD]

// ---------------------------------------------------------------------------
// Warp-level bf16 MMA helpers (Ampere-path: valid on generic compute_103)
// ---------------------------------------------------------------------------
__device__ __forceinline__ uint32_t smem_u32(const void* p) {
    uint32_t a;
    asm("{ .reg .u64 t; cvta.to.shared.u64 t, %1; cvt.u32.u64 %0, t; }" : "=r"(a) : "l"(p));
    return a;
}

__device__ __forceinline__ void ldsm4(uint32_t* r, uint32_t addr) {
    asm volatile("ldmatrix.sync.aligned.m8n8.x4.shared.b16 {%0,%1,%2,%3}, [%4];"
                 : "=r"(r[0]), "=r"(r[1]), "=r"(r[2]), "=r"(r[3]) : "r"(addr));
}

__device__ __forceinline__ void mma16816(float* c, const uint32_t* a, const uint32_t* b) {
    asm volatile(
        "mma.sync.aligned.m16n8k16.row.col.f32.bf16.bf16.f32 "
        "{%0,%1,%2,%3}, {%4,%5,%6,%7}, {%8,%9}, {%0,%1,%2,%3};"
        : "+f"(c[0]), "+f"(c[1]), "+f"(c[2]), "+f"(c[3])
        : "r"(a[0]), "r"(a[1]), "r"(a[2]), "r"(a[3]), "r"(b[0]), "r"(b[1]));
}

// split fp32 -> (hi, lo) bf16; pack pairs into u32
__device__ __forceinline__ void split4(float4 v, uint32_t& h01, uint32_t& h23,
                                       uint32_t& l01, uint32_t& l23) {
    __nv_bfloat162 h0 = __floats2bfloat162_rn(v.x, v.y);
    __nv_bfloat162 h1 = __floats2bfloat162_rn(v.z, v.w);
    __nv_bfloat162 l0 = __floats2bfloat162_rn(v.x - __bfloat162float(h0.x),
                                              v.y - __bfloat162float(h0.y));
    __nv_bfloat162 l1 = __floats2bfloat162_rn(v.z - __bfloat162float(h1.x),
                                              v.w - __bfloat162float(h1.y));
    h01 = *reinterpret_cast<uint32_t*>(&h0);
    h23 = *reinterpret_cast<uint32_t*>(&h1);
    l01 = *reinterpret_cast<uint32_t*>(&l0);
    l23 = *reinterpret_cast<uint32_t*>(&l1);
}

// ---------------------------------------------------------------------------
// Split-bf16 HMMA TN GEMM: C[m,n] = sum_k A[m,k]*B[n,k] + bias[n] (+ add[m,n])
// CTA tile 128x128, BK=32, 256 threads (8 warps, 2m x 4n), warp tile 64x32.
// smem rows padded to 40 bf16 (80B) -> conflict-free ldmatrix.
// ---------------------------------------------------------------------------
#define SSTRIDE 40

__global__ __launch_bounds__(256, 1)
void gemm_hmma(const float* __restrict__ A, const float* __restrict__ B,
               const float* __restrict__ bias, const float* __restrict__ add,
               float* __restrict__ C, int M, int N, int K)
{
    __shared__ __align__(16) uint16_t sAh[128 * SSTRIDE];
    __shared__ __align__(16) uint16_t sAl[128 * SSTRIDE];
    __shared__ __align__(16) uint16_t sBh[128 * SSTRIDE];
    __shared__ __align__(16) uint16_t sBl[128 * SSTRIDE];

    const int tid  = threadIdx.x;
    const int wid  = tid >> 5;
    const int lane = tid & 31;
    const int bm = blockIdx.y * 128;
    const int bn = blockIdx.x * 128;

    const int warp_m = (wid & 1) * 64;     // 2 warps along M
    const int warp_n = (wid >> 1) * 32;    // 4 warps along N

    // loader mapping: thread -> (row, 16-float half of the 32-float K-chunk)
    const int lrow  = tid >> 1;            // 0..127
    const int lhalf = (tid & 1) * 16;      // 0 or 16
    const float* Ag = A + (size_t)(bm + lrow) * K + lhalf;
    const float* Bg = B + (size_t)(bn + lrow) * K + lhalf;

    // ldmatrix base addresses (per-lane)
    const uint32_t aAh = smem_u32(sAh), aAl = smem_u32(sAl);
    const uint32_t aBh = smem_u32(sBh), aBl = smem_u32(sBl);
    // A: row = warp_m + mt*16 + (lane&15), col = kstep*16 + (lane>>4)*8
    const int a_r = warp_m + (lane & 15);
    const int a_c = (lane >> 4) * 8;
    // B: row = warp_n + ntp*16 + (lane>>4)*8 + (lane&7), col = kstep*16 + ((lane>>3)&1)*8
    const int b_r = warp_n + (lane >> 4) * 8 + (lane & 7);
    const int b_c = ((lane >> 3) & 1) * 8;

    float acc[4][4][4];
#pragma unroll
    for (int i = 0; i < 4; i++)
#pragma unroll
        for (int j = 0; j < 4; j++)
#pragma unroll
            for (int e = 0; e < 4; e++) acc[i][j][e] = 0.0f;

    // prefetch chunk 0
    float4 pa[4], pb[4];
#pragma unroll
    for (int j = 0; j < 4; j++) {
        pa[j] = *(const float4*)(Ag + j * 4);
        pb[j] = *(const float4*)(Bg + j * 4);
    }

    const int NCH = K >> 5;   // BK = 32
    for (int ch = 0; ch < NCH; ch++) {
        __syncthreads();   // previous chunk's ldmatrix done before overwrite
        // convert + store current chunk
#pragma unroll
        for (int j = 0; j < 4; j++) {
            const int col = lhalf + j * 4;
            const int so = lrow * SSTRIDE + col;
            uint32_t h01, h23, l01, l23;
            split4(pa[j], h01, h23, l01, l23);
            *(uint2*)&sAh[so] = make_uint2(h01, h23);
            *(uint2*)&sAl[so] = make_uint2(l01, l23);
            split4(pb[j], h01, h23, l01, l23);
            *(uint2*)&sBh[so] = make_uint2(h01, h23);
            *(uint2*)&sBl[so] = make_uint2(l01, l23);
        }
        __syncthreads();

        // prefetch next chunk (overlaps MMA work)
        if (ch + 1 < NCH) {
            const int ko = (ch + 1) * 32;
#pragma unroll
            for (int j = 0; j < 4; j++) {
                pa[j] = *(const float4*)(Ag + ko + j * 4);
                pb[j] = *(const float4*)(Bg + ko + j * 4);
            }
        }

#pragma unroll
        for (int ks = 0; ks < 2; ks++) {
            const int kc = ks * 16;
            uint32_t ah[4][4], al[4][4], bh[4][2], bl[4][2];
#pragma unroll
            for (int mt = 0; mt < 4; mt++) {
                const uint32_t off = (uint32_t)(((a_r + mt * 16) * SSTRIDE + kc + a_c) * 2);
                ldsm4(ah[mt], aAh + off);
                ldsm4(al[mt], aAl + off);
            }
#pragma unroll
            for (int ntp = 0; ntp < 2; ntp++) {
                const uint32_t off = (uint32_t)(((b_r + ntp * 16) * SSTRIDE + kc + b_c) * 2);
                uint32_t r[4];
                ldsm4(r, aBh + off);
                bh[ntp * 2][0] = r[0]; bh[ntp * 2][1] = r[1];
                bh[ntp * 2 + 1][0] = r[2]; bh[ntp * 2 + 1][1] = r[3];
                ldsm4(r, aBl + off);
                bl[ntp * 2][0] = r[0]; bl[ntp * 2][1] = r[1];
                bl[ntp * 2 + 1][0] = r[2]; bl[ntp * 2 + 1][1] = r[3];
            }
#pragma unroll
            for (int mt = 0; mt < 4; mt++) {
#pragma unroll
                for (int nt = 0; nt < 4; nt++) {
                    mma16816(acc[mt][nt], ah[mt], bh[nt]);
                    mma16816(acc[mt][nt], ah[mt], bl[nt]);
                    mma16816(acc[mt][nt], al[mt], bh[nt]);
                }
            }
        }
    }

    // epilogue
#pragma unroll
    for (int mt = 0; mt < 4; mt++) {
        const int r0 = bm + warp_m + mt * 16 + (lane >> 2);
#pragma unroll
        for (int nt = 0; nt < 4; nt++) {
            const int col = bn + warp_n + nt * 8 + (lane & 3) * 2;
            const float b0 = bias[col], b1 = bias[col + 1];
            const float* c = acc[mt][nt];
            const size_t o0 = (size_t)r0 * N + col;
            const size_t o1 = (size_t)(r0 + 8) * N + col;
            float2 v0 = make_float2(c[0] + b0, c[1] + b1);
            float2 v1 = make_float2(c[2] + b0, c[3] + b1);
            if (add != nullptr) {
                const float2 a0 = *(const float2*)&add[o0];
                const float2 a1 = *(const float2*)&add[o1];
                v0.x += a0.x; v0.y += a0.y;
                v1.x += a1.x; v1.y += a1.y;
            }
            *(float2*)&C[o0] = v0;
            *(float2*)&C[o1] = v1;
        }
    }
}

// ---------------------------------------------------------------------------
// Flash-style causal attention with ALiBi (unchanged, fp32).
// ---------------------------------------------------------------------------
__global__ __launch_bounds__(256, 2)
void attn_kernel(const float* __restrict__ qkv, const float* __restrict__ alibi,
                 float* __restrict__ ctx)
{
    __shared__ float Ks[32][HDIM];
    __shared__ float Vs[32][HDIM];

    const int h   = blockIdx.y;
    const int qb  = blockIdx.x;
    const int tid = threadIdx.x;
    const int w    = tid >> 5;
    const int lane = tid & 31;
    const int qq = lane >> 2;
    const int g  = lane & 3;
    const int q  = qb * 64 + w * 8 + qq;

    const float* qrow = qkv + (size_t)q * QKV_N + h * 384 + g * 32;
    float qreg[32];
#pragma unroll
    for (int d = 0; d < 32; d += 4) {
        const float4 v4 = *(const float4*)(qrow + d);
        qreg[d + 0] = v4.x * INV_NORM;
        qreg[d + 1] = v4.y * INV_NORM;
        qreg[d + 2] = v4.z * INV_NORM;
        qreg[d + 3] = v4.w * INV_NORM;
    }

    float acc[32];
#pragma unroll
    for (int d = 0; d < 32; d++) acc[d] = 0.0f;
    float mrun = -INFINITY;
    float lrun = 0.0f;

    const float* alibi_h = alibi + (size_t)h * SEQ;
    const int kv_end = qb * 64 + 64;

    for (int kb = 0; kb < kv_end; kb += 32) {
        for (int i = tid; i < 32 * HDIM; i += 256) {
            const int r = i >> 7, c = i & 127;
            const float* base = qkv + (size_t)(kb + r) * QKV_N + h * 384;
            Ks[r][c] = base[128 + c];
            Vs[r][c] = base[256 + c];
        }
        __syncthreads();

#pragma unroll 1
        for (int jc = 0; jc < 32; jc += 8) {
            float s[8];
#pragma unroll
            for (int jj = 0; jj < 8; jj++) s[jj] = 0.0f;

#pragma unroll
            for (int d = 0; d < 32; d += 4) {
#pragma unroll
                for (int jj = 0; jj < 8; jj++) {
                    const float4 k4 = *(const float4*)&Ks[jc + jj][g * 32 + d];
                    s[jj] += qreg[d] * k4.x + qreg[d + 1] * k4.y
                           + qreg[d + 2] * k4.z + qreg[d + 3] * k4.w;
                }
            }
#pragma unroll
            for (int jj = 0; jj < 8; jj++) {
                s[jj] += __shfl_xor_sync(0xffffffffu, s[jj], 1);
                s[jj] += __shfl_xor_sync(0xffffffffu, s[jj], 2);
            }
            float mloc = -INFINITY;
#pragma unroll
            for (int jj = 0; jj < 8; jj++) {
                const int jg = kb + jc + jj;
                s[jj] = (jg <= q) ? (s[jj] + alibi_h[jg]) : -INFINITY;
                mloc = fmaxf(mloc, s[jj]);
            }
            if (mloc > mrun) {
                const float scale = __expf(mrun - mloc);
                mrun = mloc;
                lrun *= scale;
#pragma unroll
                for (int d = 0; d < 32; d++) acc[d] *= scale;
            }
#pragma unroll
            for (int jj = 0; jj < 8; jj++) {
                const float p = __expf(s[jj] - mrun);
                lrun += p;
#pragma unroll
                for (int d = 0; d < 32; d += 4) {
                    const float4 v4 = *(const float4*)&Vs[jc + jj][g * 32 + d];
                    acc[d + 0] += p * v4.x;
                    acc[d + 1] += p * v4.y;
                    acc[d + 2] += p * v4.z;
                    acc[d + 3] += p * v4.w;
                }
            }
        }
        __syncthreads();
    }

    const float inv_l = 1.0f / lrun;
    float* out = ctx + (size_t)q * HID + h * HDIM + g * 32;
#pragma unroll
    for (int d = 0; d < 32; d += 4) {
        float4 o = make_float4(acc[d] * inv_l, acc[d + 1] * inv_l,
                               acc[d + 2] * inv_l, acc[d + 3] * inv_l);
        *(float4*)(out + d) = o;
    }
}

// ---------------------------------------------------------------------------
// Launch
// inputs: 0 hidden_states, 1 residual, 2 alibi, 3 attention_mask (unused),
//         4 W_qkv [12288,4096], 5 b_qkv, 6 W_dense [4096,4096], 7 b_dense
// ---------------------------------------------------------------------------
extern "C" void kernel_launch(void* const* d_in, const int* in_sizes, int n_in,
                              void* d_out, int out_size)
{
    const float* hs       = (const float*)d_in[0];
    const float* residual = (const float*)d_in[1];
    const float* alibi    = (const float*)d_in[2];
    const float* Wqkv     = (const float*)d_in[4];
    const float* bqkv     = (const float*)d_in[5];
    const float* Wd       = (const float*)d_in[6];
    const float* bd       = (const float*)d_in[7];
    float* out = (float*)d_out;

    float* qkv_buf = nullptr;
    float* ctx_buf = nullptr;
    cudaGetSymbolAddress((void**)&qkv_buf, g_qkv);
    cudaGetSymbolAddress((void**)&ctx_buf, g_ctx);

    // 1) fused QKV projection: [2048,4096] @ [12288,4096]^T + b_qkv
    {
        dim3 grid(QKV_N / 128, SEQ / 128);
        gemm_hmma<<<grid, 256>>>(hs, Wqkv, bqkv, nullptr, qkv_buf, SEQ, QKV_N, HID);
    }
    // 2) attention
    {
        dim3 grid(SEQ / 64, NHEAD);
        attn_kernel<<<grid, 256>>>(qkv_buf, alibi, ctx_buf);
    }
    // 3) dense projection + bias + residual
    {
        dim3 grid(HID / 128, SEQ / 128);
        gemm_hmma<<<grid, 256>>>(ctx_buf, Wd, bd, residual, out, SEQ, HID, HID);
    }
}